// round 1
// baseline (speedup 1.0000x reference)
#include <cuda_runtime.h>
#include <math.h>

// Problem constants (match reference)
#define BB 8
#define HH 256
#define WW 256
#define INFV 1e10f
#define XT 4                      // x-columns per block in the column pass
#define NBLK_COL (BB * (WW / XT)) // 512

// ---------------------------------------------------------------------------
// Scratch (device globals — no allocation allowed)
// g_a: row-pass result for EDT(1-t)  (f = INF where t < 0.5)
// g_b: row-pass result for EDT(t)    (f = INF where t > 0.5)
// ---------------------------------------------------------------------------
__device__ float g_a[BB * HH * WW];
__device__ float g_b[BB * HH * WW];
__device__ double d_partials[NBLK_COL][4]; // {sum p*dist, sum p*t, sum p*p, sum t*t}

// ---------------------------------------------------------------------------
// Pass 1: min-plus along W for both masks.
// One block per (b, y) row; thread i produces g[..., i] = min_j f[j] + (i-j)^2.
// f values live in shared; reads are uniform (broadcast, conflict-free).
// ---------------------------------------------------------------------------
__global__ __launch_bounds__(WW) void row_pass(const float* __restrict__ target) {
    const int r = blockIdx.x;   // b*HH + y
    const int i = threadIdx.x;  // x
    __shared__ float fa[WW];
    __shared__ float fb[WW];

    const float t = target[r * WW + i];
    // EDT(1-t): binary = 1-t, f = INF where (1-t) > 0.5  <=>  t < 0.5
    fa[i] = (t > 0.5f) ? 0.0f : INFV;
    // EDT(t):   binary = t,   f = INF where t > 0.5
    fb[i] = (t > 0.5f) ? INFV : 0.0f;
    __syncthreads();

    float ma = 3.0e38f, mb = 3.0e38f;
    float d = (float)i; // (i - j) at j = 0
#pragma unroll 8
    for (int j = 0; j < WW; ++j) {
        const float d2 = d * d;
        d -= 1.0f;
        ma = fminf(ma, fa[j] + d2);
        mb = fminf(mb, fb[j] + d2);
    }
    g_a[r * WW + i] = ma;
    g_b[r * WW + i] = mb;
}

// ---------------------------------------------------------------------------
// Pass 2: min-plus along H, fused with sigmoid + dice/boundary partial sums.
// Block handles XT consecutive x-columns of one batch image; thread = y.
// h[b,y,x] = min_j g[b,j,x] + (y-j)^2 ; dist = sqrt(h_a)+sqrt(h_b).
// Partial sums written to fixed per-block slots (deterministic reduction).
// ---------------------------------------------------------------------------
__global__ __launch_bounds__(HH) void col_pass(const float* __restrict__ pred,
                                               const float* __restrict__ target,
                                               const int* __restrict__ fl_ptr) {
    const int bx = blockIdx.x;            // 0 .. NBLK_COL-1
    const int b  = bx / (WW / XT);        // batch
    const int x0 = (bx % (WW / XT)) * XT; // first x column
    const int base = b * HH * WW;

    __shared__ float sa[HH][XT];
    __shared__ float sb[HH][XT];

    // Coalesced tile load of the row-pass results for these XT columns.
    for (int e = threadIdx.x; e < HH * XT; e += HH) {
        const int y  = e >> 2;  // XT == 4
        const int xl = e & 3;
        sa[y][xl] = g_a[base + y * WW + x0 + xl];
        sb[y][xl] = g_b[base + y * WW + x0 + xl];
    }
    __syncthreads();

    const int y = threadIdx.x;
    float aa0 = 3.0e38f, aa1 = 3.0e38f, aa2 = 3.0e38f, aa3 = 3.0e38f;
    float ab0 = 3.0e38f, ab1 = 3.0e38f, ab2 = 3.0e38f, ab3 = 3.0e38f;
    float d = (float)y; // (y - j) at j = 0
#pragma unroll 4
    for (int j = 0; j < HH; ++j) {
        const float d2 = d * d;
        d -= 1.0f;
        const float4 va = *reinterpret_cast<const float4*>(&sa[j][0]); // broadcast LDS.128
        const float4 vb = *reinterpret_cast<const float4*>(&sb[j][0]);
        aa0 = fminf(aa0, va.x + d2);
        aa1 = fminf(aa1, va.y + d2);
        aa2 = fminf(aa2, va.z + d2);
        aa3 = fminf(aa3, va.w + d2);
        ab0 = fminf(ab0, vb.x + d2);
        ab1 = fminf(ab1, vb.y + d2);
        ab2 = fminf(ab2, vb.z + d2);
        ab3 = fminf(ab3, vb.w + d2);
    }

    // Epilogue: sigmoid(pred), dist map, partial sums for this thread's 4 pixels.
    const int fl = *fl_ptr;
    const int gidx = base + y * WW + x0;
    const float4 pv = *reinterpret_cast<const float4*>(&pred[gidx]);
    const float4 tv = *reinterpret_cast<const float4*>(&target[gidx]);

    float pvals[XT] = {pv.x, pv.y, pv.z, pv.w};
    float tvals[XT] = {tv.x, tv.y, tv.z, tv.w};
    float ha[XT] = {aa0, aa1, aa2, aa3};
    float hb[XT] = {ab0, ab1, ab2, ab3};

    float s_pd = 0.0f, s_pt = 0.0f, s_pp = 0.0f, s_tt = 0.0f;
#pragma unroll
    for (int k = 0; k < XT; ++k) {
        float p = pvals[k];
        if (fl) p = 1.0f / (1.0f + expf(-p));
        const float dist = sqrtf(ha[k]) + sqrtf(hb[k]);
        s_pd += p * dist;
        s_pt += p * tvals[k];
        s_pp += p * p;
        s_tt += tvals[k] * tvals[k];
    }

    // Warp reduce (fp32), then combine 8 warps into doubles — fixed order.
#pragma unroll
    for (int off = 16; off > 0; off >>= 1) {
        s_pd += __shfl_down_sync(0xffffffffu, s_pd, off);
        s_pt += __shfl_down_sync(0xffffffffu, s_pt, off);
        s_pp += __shfl_down_sync(0xffffffffu, s_pp, off);
        s_tt += __shfl_down_sync(0xffffffffu, s_tt, off);
    }
    __shared__ float rs[8][4];
    const int lane = threadIdx.x & 31;
    const int warp = threadIdx.x >> 5;
    if (lane == 0) {
        rs[warp][0] = s_pd;
        rs[warp][1] = s_pt;
        rs[warp][2] = s_pp;
        rs[warp][3] = s_tt;
    }
    __syncthreads();
    if (threadIdx.x == 0) {
        double a0 = 0.0, a1 = 0.0, a2 = 0.0, a3 = 0.0;
#pragma unroll
        for (int w = 0; w < 8; ++w) {
            a0 += (double)rs[w][0];
            a1 += (double)rs[w][1];
            a2 += (double)rs[w][2];
            a3 += (double)rs[w][3];
        }
        d_partials[bx][0] = a0;
        d_partials[bx][1] = a1;
        d_partials[bx][2] = a2;
        d_partials[bx][3] = a3;
    }
}

// ---------------------------------------------------------------------------
// Finalize: deterministic tree reduction of per-block partials.
// Blocks are ordered so that blocks [g*64, (g+1)*64) belong to batch g.
// ---------------------------------------------------------------------------
__global__ __launch_bounds__(NBLK_COL) void finalize(float* __restrict__ out) {
    __shared__ double s0[NBLK_COL];
    __shared__ double s1[NBLK_COL];
    __shared__ double s2[NBLK_COL];
    __shared__ double s3[NBLK_COL];
    const int tid = threadIdx.x;
    s0[tid] = d_partials[tid][0];
    s1[tid] = d_partials[tid][1];
    s2[tid] = d_partials[tid][2];
    s3[tid] = d_partials[tid][3];
    __syncthreads();

    // Group-wise tree reduction (group = 64 blocks = one batch image).
    for (int off = 32; off >= 1; off >>= 1) {
        if ((tid & 63) < off) {
            s0[tid] += s0[tid + off];
            s1[tid] += s1[tid + off];
            s2[tid] += s2[tid + off];
            s3[tid] += s3[tid + off];
        }
        __syncthreads();
    }

    if (tid == 0) {
        double bl = 0.0, dl = 0.0;
        const double eps = 1e-6;
#pragma unroll
        for (int g = 0; g < BB; ++g) {
            const int s = g * 64;
            bl += s0[s];
            const double inter = 2.0 * s1[s];
            const double uni   = s2[s] + s3[s];
            dl += 1.0 - (inter + eps) / (uni + eps);
        }
        dl /= (double)BB;
        bl /= (double)(BB * HH * WW);
        out[0] = (float)(dl + bl); // ALPHA = BETA = 1
    }
}

// ---------------------------------------------------------------------------
extern "C" void kernel_launch(void* const* d_in, const int* in_sizes, int n_in,
                              void* d_out, int out_size) {
    const float* pred   = (const float*)d_in[0];
    const float* target = (const float*)d_in[1];
    const int*   fl     = (const int*)d_in[2];
    float* out = (float*)d_out;

    row_pass<<<BB * HH, WW>>>(target);
    col_pass<<<NBLK_COL, HH>>>(pred, target, fl);
    finalize<<<1, NBLK_COL>>>(out);
}

// round 2
// speedup vs baseline: 2.1778x; 2.1778x over previous
#include <cuda_runtime.h>
#include <math.h>

// Problem constants (match reference)
#define BB 8
#define HH 256
#define WW 256
#define XT 4                      // x-columns per block in the column pass
#define NBLK_COL (BB * (WW / XT)) // 512
#define KWIN 16                   // column-pass window radius (exactness-checked)
#define DINF 1e5f                 // distance "infinity": DINF^2 = 1e10 = reference INF

// ---------------------------------------------------------------------------
// Scratch (device globals — no allocation allowed)
// g_a[r*W+x] = drow_a^2 : squared horizontal distance to nearest t==1 pixel
// g_b[r*W+x] = drow_b^2 : squared horizontal distance to nearest t==0 pixel
// ---------------------------------------------------------------------------
__device__ float g_a[BB * HH * WW];
__device__ float g_b[BB * HH * WW];
__device__ double d_partials[NBLK_COL][4]; // {sum p*dist, sum p*t, sum p*p, sum t*t}

// ---------------------------------------------------------------------------
// Pass 1: exact 1D distance along W via jump doubling (8 steps), both masks.
// d[i] = min(d[i], d[i-s]+s, d[i+s]+s) for s = 1,2,4,...,128 is exact:
// any offset m decomposes into distinct ascending powers of two and the
// intermediate positions stay inside [min(i,j), max(i,j)].
// Writes the SQUARED distance (== reference min-plus result; 1e10 when none).
// ---------------------------------------------------------------------------
__global__ __launch_bounds__(WW) void row_scan(const float* __restrict__ target) {
    const int r = blockIdx.x;   // b*HH + y
    const int i = threadIdx.x;  // x
    __shared__ float sa[WW];
    __shared__ float sb[WW];

    const float t = target[r * WW + i];
    const bool one = (t > 0.5f);
    sa[i] = one ? 0.0f : DINF;  // dist to nearest 1 (for EDT(1-t))
    sb[i] = one ? DINF : 0.0f;  // dist to nearest 0 (for EDT(t))
    __syncthreads();

#pragma unroll
    for (int s = 1; s < WW; s <<= 1) {
        const float fs = (float)s;
        float a = sa[i], b = sb[i];
        if (i >= s)      { a = fminf(a, sa[i - s] + fs); b = fminf(b, sb[i - s] + fs); }
        if (i + s < WW)  { a = fminf(a, sa[i + s] + fs); b = fminf(b, sb[i + s] + fs); }
        __syncthreads();
        sa[i] = a; sb[i] = b;
        __syncthreads();
    }

    const float a = sa[i], b = sb[i];
    g_a[r * WW + i] = a * a;
    g_b[r * WW + i] = b * b;
}

// ---------------------------------------------------------------------------
// Pass 2: min-plus along H, windowed (exact when result <= (K+1)^2, with
// block-wide fallback to the full range otherwise), fused with sigmoid +
// dice/boundary partial sums. Block = XT columns of one image; thread = y.
// ---------------------------------------------------------------------------
__global__ __launch_bounds__(HH) void col_pass(const float* __restrict__ pred,
                                               const float* __restrict__ target,
                                               const int* __restrict__ fl_ptr) {
    const int bx = blockIdx.x;            // 0 .. NBLK_COL-1
    const int b  = bx / (WW / XT);        // batch
    const int x0 = (bx % (WW / XT)) * XT; // first x column
    const int base = b * HH * WW;

    // Rows padded by KWIN sentinel rows on each side (1e18 never wins a min).
    __shared__ __align__(16) float sa[HH + 2 * KWIN][XT];
    __shared__ __align__(16) float sb[HH + 2 * KWIN][XT];

    for (int e = threadIdx.x; e < (HH + 2 * KWIN) * XT; e += HH) {
        const int yy = (e >> 2) - KWIN;   // XT == 4
        const int xl = e & 3;
        const bool in = (yy >= 0) && (yy < HH);
        sa[e >> 2][xl] = in ? g_a[base + yy * WW + x0 + xl] : 1e18f;
        sb[e >> 2][xl] = in ? g_b[base + yy * WW + x0 + xl] : 1e18f;
    }
    __syncthreads();

    const int y = threadIdx.x;
    float aa0 = 3.0e38f, aa1 = 3.0e38f, aa2 = 3.0e38f, aa3 = 3.0e38f;
    float ab0 = 3.0e38f, ab1 = 3.0e38f, ab2 = 3.0e38f, ab3 = 3.0e38f;

#pragma unroll
    for (int dj = -KWIN; dj <= KWIN; ++dj) {
        const float d2 = (float)(dj * dj);
        const int si = y + dj + KWIN;     // in [y, y+2K] — always in-bounds
        const float4 va = *reinterpret_cast<const float4*>(&sa[si][0]);
        const float4 vb = *reinterpret_cast<const float4*>(&sb[si][0]);
        aa0 = fminf(aa0, va.x + d2); aa1 = fminf(aa1, va.y + d2);
        aa2 = fminf(aa2, va.z + d2); aa3 = fminf(aa3, va.w + d2);
        ab0 = fminf(ab0, vb.x + d2); ab1 = fminf(ab1, vb.y + d2);
        ab2 = fminf(ab2, vb.z + d2); ab3 = fminf(ab3, vb.w + d2);
    }

    // Exactness check: any candidate outside the window contributes
    // >= (K+1)^2. If every windowed min is <= that bound, it is exact.
    const float thresh = (float)((KWIN + 1) * (KWIN + 1));
    const float mymax = fmaxf(fmaxf(fmaxf(aa0, aa1), fmaxf(aa2, aa3)),
                              fmaxf(fmaxf(ab0, ab1), fmaxf(ab2, ab3)));
    const int need_full = __syncthreads_or(mymax > thresh);
    if (need_full) {
        // Exact full-range fallback (rare; still deterministic + graph-safe).
        aa0 = aa1 = aa2 = aa3 = 3.0e38f;
        ab0 = ab1 = ab2 = ab3 = 3.0e38f;
        float d = (float)y;
#pragma unroll 4
        for (int j = 0; j < HH; ++j) {
            const float d2 = d * d;
            d -= 1.0f;
            const float4 va = *reinterpret_cast<const float4*>(&sa[j + KWIN][0]);
            const float4 vb = *reinterpret_cast<const float4*>(&sb[j + KWIN][0]);
            aa0 = fminf(aa0, va.x + d2); aa1 = fminf(aa1, va.y + d2);
            aa2 = fminf(aa2, va.z + d2); aa3 = fminf(aa3, va.w + d2);
            ab0 = fminf(ab0, vb.x + d2); ab1 = fminf(ab1, vb.y + d2);
            ab2 = fminf(ab2, vb.z + d2); ab3 = fminf(ab3, vb.w + d2);
        }
    }

    // Epilogue: sigmoid(pred), dist map, per-thread partial sums.
    const int fl = *fl_ptr;
    const int gidx = base + y * WW + x0;
    const float4 pv = *reinterpret_cast<const float4*>(&pred[gidx]);
    const float4 tv = *reinterpret_cast<const float4*>(&target[gidx]);

    float pvals[XT] = {pv.x, pv.y, pv.z, pv.w};
    float tvals[XT] = {tv.x, tv.y, tv.z, tv.w};
    float ha[XT] = {aa0, aa1, aa2, aa3};
    float hb[XT] = {ab0, ab1, ab2, ab3};

    float s_pd = 0.0f, s_pt = 0.0f, s_pp = 0.0f, s_tt = 0.0f;
#pragma unroll
    for (int k = 0; k < XT; ++k) {
        float p = pvals[k];
        if (fl) p = 1.0f / (1.0f + expf(-p));
        const float dist = sqrtf(ha[k]) + sqrtf(hb[k]);
        s_pd += p * dist;
        s_pt += p * tvals[k];
        s_pp += p * p;
        s_tt += tvals[k] * tvals[k];
    }

    // Warp reduce, then combine 8 warps into doubles — fixed order.
#pragma unroll
    for (int off = 16; off > 0; off >>= 1) {
        s_pd += __shfl_down_sync(0xffffffffu, s_pd, off);
        s_pt += __shfl_down_sync(0xffffffffu, s_pt, off);
        s_pp += __shfl_down_sync(0xffffffffu, s_pp, off);
        s_tt += __shfl_down_sync(0xffffffffu, s_tt, off);
    }
    __shared__ float rs[8][4];
    const int lane = threadIdx.x & 31;
    const int warp = threadIdx.x >> 5;
    if (lane == 0) {
        rs[warp][0] = s_pd; rs[warp][1] = s_pt;
        rs[warp][2] = s_pp; rs[warp][3] = s_tt;
    }
    __syncthreads();
    if (threadIdx.x == 0) {
        double a0 = 0.0, a1 = 0.0, a2 = 0.0, a3 = 0.0;
#pragma unroll
        for (int w = 0; w < 8; ++w) {
            a0 += (double)rs[w][0]; a1 += (double)rs[w][1];
            a2 += (double)rs[w][2]; a3 += (double)rs[w][3];
        }
        d_partials[bx][0] = a0; d_partials[bx][1] = a1;
        d_partials[bx][2] = a2; d_partials[bx][3] = a3;
    }
}

// ---------------------------------------------------------------------------
// Finalize: deterministic tree reduction of per-block partials.
// Blocks [g*64, (g+1)*64) belong to batch g.
// ---------------------------------------------------------------------------
__global__ __launch_bounds__(NBLK_COL) void finalize(float* __restrict__ out) {
    __shared__ double s0[NBLK_COL];
    __shared__ double s1[NBLK_COL];
    __shared__ double s2[NBLK_COL];
    __shared__ double s3[NBLK_COL];
    const int tid = threadIdx.x;
    s0[tid] = d_partials[tid][0];
    s1[tid] = d_partials[tid][1];
    s2[tid] = d_partials[tid][2];
    s3[tid] = d_partials[tid][3];
    __syncthreads();

    for (int off = 32; off >= 1; off >>= 1) {
        if ((tid & 63) < off) {
            s0[tid] += s0[tid + off];
            s1[tid] += s1[tid + off];
            s2[tid] += s2[tid + off];
            s3[tid] += s3[tid + off];
        }
        __syncthreads();
    }

    if (tid == 0) {
        double bl = 0.0, dl = 0.0;
        const double eps = 1e-6;
#pragma unroll
        for (int g = 0; g < BB; ++g) {
            const int s = g * 64;
            bl += s0[s];
            const double inter = 2.0 * s1[s];
            const double uni   = s2[s] + s3[s];
            dl += 1.0 - (inter + eps) / (uni + eps);
        }
        dl /= (double)BB;
        bl /= (double)(BB * HH * WW);
        out[0] = (float)(dl + bl); // ALPHA = BETA = 1
    }
}

// ---------------------------------------------------------------------------
extern "C" void kernel_launch(void* const* d_in, const int* in_sizes, int n_in,
                              void* d_out, int out_size) {
    const float* pred   = (const float*)d_in[0];
    const float* target = (const float*)d_in[1];
    const int*   fl     = (const int*)d_in[2];
    float* out = (float*)d_out;

    row_scan<<<BB * HH, WW>>>(target);
    col_pass<<<NBLK_COL, HH>>>(pred, target, fl);
    finalize<<<1, NBLK_COL>>>(out);
}

// round 3
// speedup vs baseline: 2.3178x; 1.0643x over previous
#include <cuda_runtime.h>
#include <math.h>

// Problem constants (match reference)
#define BB 8
#define HH 256
#define WW 256
#define XT 4                      // x-columns per block in the column pass
#define NBLK_COL (BB * (WW / XT)) // 512
#define KWIN 8                    // column-pass window radius (exactness-checked)
#define TROWS (HH + 2 * KWIN)     // padded tile rows (272)
#define NW 8                      // 256-bit row mask = 8 words

// ---------------------------------------------------------------------------
// Scratch (device globals — no allocation allowed)
// ---------------------------------------------------------------------------
__device__ unsigned g_mask[BB * HH * NW];      // bit j of word w: t[row, w*32+j] > 0.5
__device__ double d_partials[NBLK_COL][4];     // {sum p*dist, sum p*t, sum p*p, sum t*t}
__device__ int g_cnt;

// ---------------------------------------------------------------------------
// Kernel 1: build per-row bitmasks (1 ballot per warp) + reset the counter.
// ---------------------------------------------------------------------------
__global__ __launch_bounds__(WW) void mask_kernel(const float* __restrict__ target) {
    const int r = blockIdx.x;   // b*HH + y
    const int i = threadIdx.x;  // x
    if (r == 0 && i == 0) g_cnt = 0;
    const float t = target[r * WW + i];
    const unsigned bal = __ballot_sync(0xffffffffu, t > 0.5f);
    if ((i & 31) == 0) g_mask[r * NW + (i >> 5)] = bal;
}

// ---------------------------------------------------------------------------
// Nearest-set-bit distances (to 1 and to 0) within a 256-bit row mask.
// i: bit position. Returns squared distances via da (to a set bit) and
// db (to a clear bit). 1e5 -> squared 1e10 matches the reference INF.
// ---------------------------------------------------------------------------
__device__ __forceinline__ void row_dists(const unsigned* __restrict__ m, int i,
                                          float& da, float& db) {
    const int wi = i >> 5, bi = i & 31;
    const unsigned lowmask = (2u << bi) - 1u;     // bits 0..bi (bi=31 -> all)
    const unsigned himask  = ~((1u << bi) - 1u);  // bits bi..31
    const unsigned mw = m[wi];

    int d1 = 100000, d0 = 100000;

    // --- nearest 1 ---
    {
        unsigned wl = mw & lowmask;
        int dl = 100000;
        if (wl) dl = bi - (31 - __clz(wl));
        else {
            for (int k = wi - 1; k >= 0; --k) {
                unsigned mk = m[k];
                if (mk) { dl = i - (k * 32 + 31 - __clz(mk)); break; }
            }
        }
        unsigned wr = mw & himask;
        int dr = 100000;
        if (wr) dr = (__ffs(wr) - 1) - bi;
        else {
            for (int k = wi + 1; k < NW; ++k) {
                unsigned mk = m[k];
                if (mk) { dr = (k * 32 + __ffs(mk) - 1) - i; break; }
            }
        }
        d1 = min(dl, dr);
    }
    // --- nearest 0 (complement) ---
    {
        unsigned cw = ~mw;
        unsigned wl = cw & lowmask;
        int dl = 100000;
        if (wl) dl = bi - (31 - __clz(wl));
        else {
            for (int k = wi - 1; k >= 0; --k) {
                unsigned mk = ~m[k];
                if (mk) { dl = i - (k * 32 + 31 - __clz(mk)); break; }
            }
        }
        unsigned wr = cw & himask;
        int dr = 100000;
        if (wr) dr = (__ffs(wr) - 1) - bi;
        else {
            for (int k = wi + 1; k < NW; ++k) {
                unsigned mk = ~m[k];
                if (mk) { dr = (k * 32 + __ffs(mk) - 1) - i; break; }
            }
        }
        d0 = min(dl, dr);
    }
    const float f1 = (float)d1, f0 = (float)d0;
    da = f1 * f1;   // squared dist to nearest 1  (row pass of EDT(1-t))
    db = f0 * f0;   // squared dist to nearest 0  (row pass of EDT(t))
}

// ---------------------------------------------------------------------------
// Kernel 2: fused column min-plus (windowed, exactness-checked) + sigmoid +
// dice/boundary partials + deterministic last-block finalize.
// Block = XT columns of one image; thread = y.
// ---------------------------------------------------------------------------
__global__ __launch_bounds__(HH) void col_fused(const float* __restrict__ pred,
                                                const float* __restrict__ target,
                                                const int* __restrict__ fl_ptr,
                                                float* __restrict__ out) {
    const int bx = blockIdx.x;            // 0 .. NBLK_COL-1
    const int b  = bx / (WW / XT);        // batch
    const int x0 = (bx % (WW / XT)) * XT; // first x column
    const int base = b * HH * WW;

    __shared__ unsigned smask[HH * NW];                 // 8KB: full image row masks
    __shared__ __align__(16) float sa[TROWS][XT];       // row-pass dist^2 to 1
    __shared__ __align__(16) float sb[TROWS][XT];       // row-pass dist^2 to 0

    // Load this image's row masks (coalesced).
    for (int e = threadIdx.x; e < HH * NW; e += HH)
        smask[e] = g_mask[b * HH * NW + e];
    __syncthreads();

    // Build padded tile from masks on the fly.
    for (int e = threadIdx.x; e < TROWS * XT; e += HH) {
        const int ry = e >> 2;            // XT == 4
        const int yy = ry - KWIN;
        const int xl = e & 3;
        if (yy >= 0 && yy < HH) {
            float da, db;
            row_dists(&smask[yy * NW], x0 + xl, da, db);
            sa[ry][xl] = da; sb[ry][xl] = db;
        } else {
            sa[ry][xl] = 1e18f; sb[ry][xl] = 1e18f;
        }
    }
    __syncthreads();

    const int y = threadIdx.x;
    float aa0 = 3.0e38f, aa1 = 3.0e38f, aa2 = 3.0e38f, aa3 = 3.0e38f;
    float ab0 = 3.0e38f, ab1 = 3.0e38f, ab2 = 3.0e38f, ab3 = 3.0e38f;

#pragma unroll
    for (int dj = -KWIN; dj <= KWIN; ++dj) {
        const float d2 = (float)(dj * dj);
        const int si = y + dj + KWIN;     // always in-bounds of padded tile
        const float4 va = *reinterpret_cast<const float4*>(&sa[si][0]);
        const float4 vb = *reinterpret_cast<const float4*>(&sb[si][0]);
        aa0 = fminf(aa0, va.x + d2); aa1 = fminf(aa1, va.y + d2);
        aa2 = fminf(aa2, va.z + d2); aa3 = fminf(aa3, va.w + d2);
        ab0 = fminf(ab0, vb.x + d2); ab1 = fminf(ab1, vb.y + d2);
        ab2 = fminf(ab2, vb.z + d2); ab3 = fminf(ab3, vb.w + d2);
    }

    // Exactness: candidates outside the window contribute >= (K+1)^2.
    const float thresh = (float)((KWIN + 1) * (KWIN + 1));
    const float mymax = fmaxf(fmaxf(fmaxf(aa0, aa1), fmaxf(aa2, aa3)),
                              fmaxf(fmaxf(ab0, ab1), fmaxf(ab2, ab3)));
    const int need_full = __syncthreads_or(mymax > thresh);
    if (need_full) {
        aa0 = aa1 = aa2 = aa3 = 3.0e38f;
        ab0 = ab1 = ab2 = ab3 = 3.0e38f;
        float d = (float)y;
#pragma unroll 4
        for (int j = 0; j < HH; ++j) {
            const float d2 = d * d;
            d -= 1.0f;
            const float4 va = *reinterpret_cast<const float4*>(&sa[j + KWIN][0]);
            const float4 vb = *reinterpret_cast<const float4*>(&sb[j + KWIN][0]);
            aa0 = fminf(aa0, va.x + d2); aa1 = fminf(aa1, va.y + d2);
            aa2 = fminf(aa2, va.z + d2); aa3 = fminf(aa3, va.w + d2);
            ab0 = fminf(ab0, vb.x + d2); ab1 = fminf(ab1, vb.y + d2);
            ab2 = fminf(ab2, vb.z + d2); ab3 = fminf(ab3, vb.w + d2);
        }
    }

    // Epilogue: sigmoid(pred), dist map, per-thread partial sums.
    const int fl = *fl_ptr;
    const int gidx = base + y * WW + x0;
    const float4 pv = *reinterpret_cast<const float4*>(&pred[gidx]);
    const float4 tv = *reinterpret_cast<const float4*>(&target[gidx]);

    float pvals[XT] = {pv.x, pv.y, pv.z, pv.w};
    float tvals[XT] = {tv.x, tv.y, tv.z, tv.w};
    float ha[XT] = {aa0, aa1, aa2, aa3};
    float hb[XT] = {ab0, ab1, ab2, ab3};

    float s_pd = 0.0f, s_pt = 0.0f, s_pp = 0.0f, s_tt = 0.0f;
#pragma unroll
    for (int k = 0; k < XT; ++k) {
        float p = pvals[k];
        if (fl) p = 1.0f / (1.0f + expf(-p));
        const float dist = sqrtf(ha[k]) + sqrtf(hb[k]);
        s_pd += p * dist;
        s_pt += p * tvals[k];
        s_pp += p * p;
        s_tt += tvals[k] * tvals[k];
    }

    // Warp reduce, then combine 8 warps into doubles — fixed order.
#pragma unroll
    for (int off = 16; off > 0; off >>= 1) {
        s_pd += __shfl_down_sync(0xffffffffu, s_pd, off);
        s_pt += __shfl_down_sync(0xffffffffu, s_pt, off);
        s_pp += __shfl_down_sync(0xffffffffu, s_pp, off);
        s_tt += __shfl_down_sync(0xffffffffu, s_tt, off);
    }
    __shared__ float rs[8][4];
    const int lane = threadIdx.x & 31;
    const int warp = threadIdx.x >> 5;
    if (lane == 0) {
        rs[warp][0] = s_pd; rs[warp][1] = s_pt;
        rs[warp][2] = s_pp; rs[warp][3] = s_tt;
    }
    __syncthreads();

    __shared__ int s_last;
    if (threadIdx.x == 0) {
        double a0 = 0.0, a1 = 0.0, a2 = 0.0, a3 = 0.0;
#pragma unroll
        for (int w = 0; w < 8; ++w) {
            a0 += (double)rs[w][0]; a1 += (double)rs[w][1];
            a2 += (double)rs[w][2]; a3 += (double)rs[w][3];
        }
        d_partials[bx][0] = a0; d_partials[bx][1] = a1;
        d_partials[bx][2] = a2; d_partials[bx][3] = a3;
        __threadfence();
        const int old = atomicAdd(&g_cnt, 1);
        s_last = (old == NBLK_COL - 1);
    }
    __syncthreads();
    if (!s_last) return;

    // -------- last block: deterministic finalize (fixed slots, fixed order) --
    __threadfence();
    __shared__ double f0[NBLK_COL];
    __shared__ double f1[NBLK_COL];
    __shared__ double f2[NBLK_COL];
    __shared__ double f3[NBLK_COL];
    const int tid = threadIdx.x;
    for (int i = tid; i < NBLK_COL; i += HH) {
        f0[i] = d_partials[i][0];
        f1[i] = d_partials[i][1];
        f2[i] = d_partials[i][2];
        f3[i] = d_partials[i][3];
    }
    __syncthreads();
    for (int off = 32; off >= 1; off >>= 1) {
        for (int i = tid; i < NBLK_COL; i += HH) {
            if ((i & 63) < off) {
                f0[i] += f0[i + off];
                f1[i] += f1[i + off];
                f2[i] += f2[i + off];
                f3[i] += f3[i + off];
            }
        }
        __syncthreads();
    }
    if (tid == 0) {
        double bl = 0.0, dl = 0.0;
        const double eps = 1e-6;
#pragma unroll
        for (int g = 0; g < BB; ++g) {
            const int s = g * 64;
            bl += f0[s];
            const double inter = 2.0 * f1[s];
            const double uni   = f2[s] + f3[s];
            dl += 1.0 - (inter + eps) / (uni + eps);
        }
        dl /= (double)BB;
        bl /= (double)(BB * HH * WW);
        out[0] = (float)(dl + bl); // ALPHA = BETA = 1
    }
}

// ---------------------------------------------------------------------------
extern "C" void kernel_launch(void* const* d_in, const int* in_sizes, int n_in,
                              void* d_out, int out_size) {
    const float* pred   = (const float*)d_in[0];
    const float* target = (const float*)d_in[1];
    const int*   fl     = (const int*)d_in[2];
    float* out = (float*)d_out;

    mask_kernel<<<BB * HH, WW>>>(target);
    col_fused<<<NBLK_COL, HH>>>(pred, target, fl, out);
}